// round 14
// baseline (speedup 1.0000x reference)
#include <cuda_runtime.h>
#include <math.h>

// Problem constants
#define BATCH 128
#define HDIM  512
#define IDIM  512
#define NG    (6 * HDIM)   // 3072 gate columns
#define INV_SQRT_H 0.04419417382415922f  // 1/sqrt(512)

// Output layout: concat(h_t [B,H], C_t [B,H,H], m_t [B,H], n_t [B,H])
#define OUT_H 0
#define OUT_C (BATCH * HDIM)                                // 65536
#define OUT_M (OUT_C + (long)BATCH * HDIM * HDIM)           // 33619968
#define OUT_N (OUT_M + BATCH * HDIM)                        // 33685504

#define NSPLIT 4
#define MCHUNK 64          // batch-chunk height for pipeline overlap
#define GEMM_BLOCKS 192    // 48 n-tiles x 4 splits per chunk
#define STREAM_BLOCKS 4096 // 64 batches x 64 blocks per chunk

// Scratch (device globals — no allocation allowed)
__device__ float g_part[NSPLIT][BATCH * NG];  // split-K partial gate sums
__device__ float g_q[BATCH * HDIM];
__device__ float g_f[BATCH * HDIM];
__device__ float g_add[BATCH * HDIM];
__device__ float g_o[BATCH * HDIM];
__device__ float g_sumq[BATCH];
__device__ float g_invden[BATCH];

// ---------------------------------------------------------------------------
// GEMM role: partial gates = x[mbase:mbase+64] @ W^T, split-K=4, fp32 FFMA.
// BM=64 (chunk), BN=64, BK=16, 256 threads, 4x4/thread — the R8-proven
// per-warp structure (10.4 warps/SM when 192 blocks run alone).
// ---------------------------------------------------------------------------
#define CBN 64
#define CBK 16
#define CKSPLIT (IDIM / NSPLIT)   // 128
#define CPAD 68                   // 272B row stride: 16B multiple

#define GEMM_SMEM (2 * CBK * CPAD)   // floats

__device__ __forceinline__ void gemm_role(
    int gblk, int mbase,
    const float* __restrict__ x, const float* __restrict__ Wm,
    int tid, float* sh)
{
    float (*sA)[CPAD] = reinterpret_cast<float(*)[CPAD]>(sh);
    float (*sB)[CPAD] = reinterpret_cast<float(*)[CPAD]>(sh + CBK * CPAD);

    int n0 = (gblk % 48) * CBN;
    int zs = gblk / 48;               // 0..3
    int kbase = zs * CKSPLIT;
    float* dst = &g_part[zs][0];

    int tx = tid & 15;                // 16 col-groups * 4 = 64 cols
    int ty = tid >> 4;                // 16 row-groups * 4 = 64 rows

    // loaders: 64 rows x 16 k = 256 float4 -> exactly 1 per thread
    int lrow = tid >> 2, lkq = (tid & 3) * 4;
    const float* Aptr = x  + (long)(mbase + lrow) * IDIM + kbase + lkq;
    const float* Bptr = Wm + (long)(n0 + lrow) * IDIM + kbase + lkq;

    float acc[4][4];
#pragma unroll
    for (int i = 0; i < 4; i++)
#pragma unroll
        for (int j = 0; j < 4; j++) acc[i][j] = 0.f;

    float4 pa = *reinterpret_cast<const float4*>(Aptr);
    float4 pb = *reinterpret_cast<const float4*>(Bptr);

    for (int kt = 0; kt < CKSPLIT; kt += CBK) {
        sA[lkq + 0][lrow] = pa.x; sA[lkq + 1][lrow] = pa.y;
        sA[lkq + 2][lrow] = pa.z; sA[lkq + 3][lrow] = pa.w;
        sB[lkq + 0][lrow] = pb.x; sB[lkq + 1][lrow] = pb.y;
        sB[lkq + 2][lrow] = pb.z; sB[lkq + 3][lrow] = pb.w;
        __syncthreads();

        if (kt + CBK < CKSPLIT) {
            pa = *reinterpret_cast<const float4*>(Aptr + kt + CBK);
            pb = *reinterpret_cast<const float4*>(Bptr + kt + CBK);
        }

#pragma unroll
        for (int k = 0; k < CBK; k++) {
            float4 a = *reinterpret_cast<const float4*>(&sA[k][ty * 4]);
            float4 b = *reinterpret_cast<const float4*>(&sB[k][tx * 4]);
            float av[4] = {a.x, a.y, a.z, a.w};
            float bv[4] = {b.x, b.y, b.z, b.w};
#pragma unroll
            for (int i = 0; i < 4; i++)
#pragma unroll
                for (int j = 0; j < 4; j++) acc[i][j] += av[i] * bv[j];
        }
        __syncthreads();
    }

#pragma unroll
    for (int i = 0; i < 4; i++) {
        int m = mbase + ty * 4 + i;
        float4 o = make_float4(acc[i][0], acc[i][1], acc[i][2], acc[i][3]);
        *reinterpret_cast<float4*>(dst + (long)m * NG + n0 + tx * 4) = o;
    }
}

// ---------------------------------------------------------------------------
// Stream role: one warp per C row. C_t = f*C_prev + add, fused
// Cq = f*dot(row,q) + add*sum_q, h_t written directly. (R8-proven best.)
// ---------------------------------------------------------------------------
__device__ __forceinline__ void stream_role(
    const float* __restrict__ Cprev, float* __restrict__ out,
    int bbase, int sblk, int tid, float* sq)
{
    int b  = bbase + (sblk >> 6);
    int rg = sblk & 63;

    const float* qrow = g_q + (long)b * HDIM;
    reinterpret_cast<float2*>(sq)[tid] = reinterpret_cast<const float2*>(qrow)[tid];
    __syncthreads();

    int warp = tid >> 5, lane = tid & 31;
    int i = rg * 8 + warp;
    int bh = b * HDIM + i;
    long rowoff = ((long)b * HDIM + i) * HDIM;

    float fv = g_f[bh];
    float av = g_add[bh];

    const float4* src = reinterpret_cast<const float4*>(Cprev + rowoff);
    float4*       dst = reinterpret_cast<float4*>(out + OUT_C + rowoff);
    const float4* qsv = reinterpret_cast<const float4*>(sq);

    float4 c[4], qv[4];
#pragma unroll
    for (int u = 0; u < 4; u++) c[u] = __ldcs(&src[lane + u * 32]);
#pragma unroll
    for (int u = 0; u < 4; u++) qv[u] = qsv[lane + u * 32];

    float dot = 0.f;
#pragma unroll
    for (int u = 0; u < 4; u++) {
        dot += c[u].x * qv[u].x + c[u].y * qv[u].y
             + c[u].z * qv[u].z + c[u].w * qv[u].w;
        float4 o;
        o.x = fv * c[u].x + av;
        o.y = fv * c[u].y + av;
        o.z = fv * c[u].z + av;
        o.w = fv * c[u].w + av;
        __stcs(&dst[lane + u * 32], o);
    }
    for (int s = 16; s; s >>= 1) dot += __shfl_xor_sync(0xffffffffu, dot, s);
    if (lane == 0) {
        float cq = fv * dot + av * g_sumq[b];
        out[OUT_H + bh] = g_o[bh] * cq * g_invden[b];
    }
}

// ---------------------------------------------------------------------------
// Kernels
// ---------------------------------------------------------------------------
__global__ __launch_bounds__(256) void gemm_chunk_kernel(
    const float* __restrict__ x, const float* __restrict__ Wm, int mbase)
{
    __shared__ float sh[GEMM_SMEM];
    gemm_role(blockIdx.x, mbase, x, Wm, threadIdx.x, sh);
}

__global__ __launch_bounds__(256) void stream_chunk_kernel(
    const float* __restrict__ Cprev, float* __restrict__ out, int bbase)
{
    __shared__ float sh[HDIM];
    stream_role(Cprev, out, bbase, blockIdx.x, threadIdx.x, sh);
}

// The overlap launch: GEMM role blocks FIRST (start in wave 1, run long under
// the DRAM-bound stream blocks). stream(chunk 0) || GEMM(chunk 1) — no
// inter-block dependency inside this grid.
__global__ __launch_bounds__(256) void fused_stream_gemm_kernel(
    const float* __restrict__ Cprev, float* __restrict__ out,
    const float* __restrict__ x, const float* __restrict__ Wm)
{
    __shared__ float sh[GEMM_SMEM];   // stream role uses first 512 floats
    if (blockIdx.x < GEMM_BLOCKS)
        gemm_role(blockIdx.x, MCHUNK, x, Wm, threadIdx.x, sh);
    else
        stream_role(Cprev, out, 0, blockIdx.x - GEMM_BLOCKS, threadIdx.x, sh);
}

// ---------------------------------------------------------------------------
// K2: fused partial-sum (4 splits) + bias + gate elementwise + per-batch
// reductions, for one 64-batch chunk. One block (512 thr) per batch.
// ---------------------------------------------------------------------------
__global__ __launch_bounds__(512) void gatered_kernel(
    const float* __restrict__ m_prev,
    const float* __restrict__ n_prev,
    const float* __restrict__ bias,
    float* __restrict__ out, int bbase)
{
    int b = bbase + blockIdx.x;
    int h = threadIdx.x;           // 0..511
    int idx = b * HDIM + h;
    long base = (long)b * NG;

    float gv[6];
#pragma unroll
    for (int s = 0; s < 6; s++) {
        int col = s * HDIM + h;
        float v = (g_part[0][base + col] + g_part[1][base + col])
                + (g_part[2][base + col] + g_part[3][base + col]);
        gv[s] = v + bias[col];
    }
    float ig = gv[0], fg = gv[1], og = gv[2], qv = gv[3], kg = gv[4], vg = gv[5];

    float mp = m_prev[idx];
    float mt = fmaxf(fg + mp, ig);
    float it = expf(ig - mt);
    float ft = expf(fg + mp - mt);
    float kt = INV_SQRT_H * kg;
    float nt = ft * n_prev[idx] + it * kt;

    out[OUT_M + idx] = mt;
    out[OUT_N + idx] = nt;
    g_q[idx]   = qv;
    g_f[idx]   = ft;
    g_add[idx] = it * vg * kt;
    g_o[idx]   = 1.f / (1.f + expf(-og));

    float sq = qv;
    float nq = nt * qv;
    for (int s = 16; s; s >>= 1) {
        sq += __shfl_xor_sync(0xffffffffu, sq, s);
        nq += __shfl_xor_sync(0xffffffffu, nq, s);
    }
    __shared__ float s1[16], s2[16];
    int warp = h >> 5, lane = h & 31;
    if (lane == 0) { s1[warp] = sq; s2[warp] = nq; }
    __syncthreads();
    if (warp == 0) {
        sq = (lane < 16) ? s1[lane] : 0.f;
        nq = (lane < 16) ? s2[lane] : 0.f;
        for (int s = 8; s; s >>= 1) {
            sq += __shfl_xor_sync(0xffffffffu, sq, s);
            nq += __shfl_xor_sync(0xffffffffu, nq, s);
        }
        if (lane == 0) {
            g_sumq[b]   = sq;
            g_invden[b] = 1.f / fmaxf(fabsf(nq), 1e-6f);
        }
    }
}

// ---------------------------------------------------------------------------
// Launch. Inputs (metadata order): x, h_prev, C_prev, m_prev, n_prev, W, b
// Pipeline: G0 | K0 | (S0 || G1) | K1 | S1
// ---------------------------------------------------------------------------
extern "C" void kernel_launch(void* const* d_in, const int* in_sizes, int n_in,
                              void* d_out, int out_size)
{
    const float* x      = (const float*)d_in[0];
    // d_in[1] = h_prev (unused by reference)
    const float* C_prev = (const float*)d_in[2];
    const float* m_prev = (const float*)d_in[3];
    const float* n_prev = (const float*)d_in[4];
    const float* W      = (const float*)d_in[5];
    const float* bias   = (const float*)d_in[6];
    float* out = (float*)d_out;

    // G0: gates for batches 0..63
    gemm_chunk_kernel<<<GEMM_BLOCKS, 256>>>(x, W, 0);

    // K0: gate math + reductions for batches 0..63
    gatered_kernel<<<MCHUNK, 512>>>(m_prev, n_prev, bias, out, 0);

    // S0 || G1: stream batches 0..63 while computing gates for 64..127
    fused_stream_gemm_kernel<<<GEMM_BLOCKS + STREAM_BLOCKS, 256>>>(C_prev, out, x, W);

    // K1: gate math + reductions for batches 64..127
    gatered_kernel<<<MCHUNK, 512>>>(m_prev, n_prev, bias, out, MCHUNK);

    // S1: stream batches 64..127
    stream_chunk_kernel<<<STREAM_BLOCKS, 256>>>(C_prev, out, MCHUNK);
}